// round 15
// baseline (speedup 1.0000x reference)
#include <cuda_runtime.h>
#include <cuda_fp16.h>
#include <math.h>
#include <stdint.h>

#define BATCH 32768
#define DIM   256
#define CBK   1024
#define LVL   8
#define BM    128
#define GRID  (BATCH / BM)           // 256
#define MU    7e-4f                  // = 2*B, B = hard 2-pass fp16 score-error bound (3.5e-4)

// smem byte offsets
#define SO_A    0                    // A tile [128 rows][512 = xh|xl] fp16, 1024B rows = 131072
#define SO_B    131072               // B slabs 2 x [128 codes][64 k] fp16 = 32768
#define SO_EE   163840               // 1024 floats = 4096
#define SO_CV   167936               // cand values [128 rows][32] = 16384
#define SO_CI   184320               // cand indices = 16384
#define SO_IDX  200704               // 128 ints (+pad)
#define SO_RED  201216               // 256 floats
#define SO_CNT  202240               // [0]=rescue cnt, [1]=fullscan cnt (+pad)
#define SO_RQ   202256               // 128 entries x 12 ints = 6144
#define SO_FQ   208400               // 128 ints (+pad)
#define SMEM_BYTES 208912

// ---------------- device scratch ----------------
__device__ float g_resid[BATCH * DIM];
__device__ float g_qsum [BATCH * DIM];
__device__ float g_xx   [BATCH];
__device__ float g_ee   [LVL * CBK];
__device__ int   g_idx  [BATCH * LVL];
__device__ float g_commit_part[LVL * GRID];
__device__ int   g_counts[CBK];
__device__ __half g_ah[BATCH * DIM];        // residual hi (fp16)
__device__ __half g_al[BATCH * DIM];        // residual lo (fp16)
__device__ __half g_bh[LVL * CBK * DIM];    // codebook fp16

// ---------------- helpers ----------------
__device__ __forceinline__ uint32_t smem_u32(const void* p) {
    uint32_t a;
    asm("{ .reg .u64 t; cvta.to.shared.u64 t, %1; cvt.u32.u64 %0, t; }" : "=r"(a) : "l"(p));
    return a;
}
#define CP16(dst, src) asm volatile("cp.async.cg.shared.global [%0], [%1], 16;" :: "r"(dst), "l"(src))
#define CPCOMMIT()     asm volatile("cp.async.commit_group;" ::: "memory")
#define CPWAIT1()      asm volatile("cp.async.wait_group 1;" ::: "memory")
#define CPWAIT0()      asm volatile("cp.async.wait_group 0;" ::: "memory")

__device__ __forceinline__ void ldsm_x4(uint32_t* r, uint32_t addr) {
    asm volatile("ldmatrix.sync.aligned.m8n8.x4.shared.b16 {%0,%1,%2,%3}, [%4];"
        : "=r"(r[0]), "=r"(r[1]), "=r"(r[2]), "=r"(r[3]) : "r"(addr));
}
__device__ __forceinline__ void mma_f16(float* d, const uint32_t* a, const uint32_t* b) {
    asm volatile("mma.sync.aligned.m16n8k16.row.col.f32.f16.f16.f32 "
        "{%0,%1,%2,%3}, {%4,%5,%6,%7}, {%8,%9}, {%0,%1,%2,%3};"
        : "+f"(d[0]), "+f"(d[1]), "+f"(d[2]), "+f"(d[3])
        : "r"(a[0]), "r"(a[1]), "r"(a[2]), "r"(a[3]), "r"(b[0]), "r"(b[1]));
}

// ---------------- prep kernels ----------------
__global__ void k_prepB(const float* __restrict__ emb)
{
    int i = blockIdx.x * blockDim.x + threadIdx.x;
    if (i >= LVL * CBK * DIM) return;
    g_bh[i] = __float2half_rn(emb[i]);
}

__global__ void k_eeinit(const float* __restrict__ emb)
{
    int gt = blockIdx.x * blockDim.x + threadIdx.x;
    if (gt < CBK) g_counts[gt] = 0;
    int gw   = blockIdx.x * (blockDim.x >> 5) + (threadIdx.x >> 5);
    int lane = threadIdx.x & 31;
    if (gw >= LVL * CBK) return;
    const float* r = emb + (size_t)gw * DIM;
    float s = 0.f;
#pragma unroll
    for (int j = 0; j < 8; j++) { float v = r[lane + 32 * j]; s = fmaf(v, v, s); }
#pragma unroll
    for (int o = 16; o; o >>= 1) s += __shfl_xor_sync(0xffffffffu, s, o);
    if (!lane) g_ee[gw] = s;
}

__global__ void k_prepA(const float* __restrict__ z)
{
    int gw   = blockIdx.x * (blockDim.x >> 5) + (threadIdx.x >> 5);
    int lane = threadIdx.x & 31;
    if (gw >= BATCH) return;
    const float* r = z + (size_t)gw * DIM;
    float s = 0.f;
#pragma unroll
    for (int j = 0; j < 8; j++) {
        float v = r[lane + 32 * j];
        __half h = __float2half_rn(v);
        g_ah[(size_t)gw * DIM + lane + 32 * j] = h;
        g_al[(size_t)gw * DIM + lane + 32 * j] = __float2half_rn(v - __half2float(h));
        s = fmaf(v, v, s);
    }
#pragma unroll
    for (int o = 16; o; o >>= 1) s += __shfl_xor_sync(0xffffffffu, s, o);
    if (!lane) g_xx[gw] = s;
}

// ---------------- main per-level kernel: 2-pass fp16 HMMA + lossless top-2 + 3-way --
// 256 CTAs x 256 threads (8 warps = 2m x 4n, warp tile 64x32, acc[4][4][4]).
// A = [128][512 fp16: xh|xl] resident; B = Bh-only slabs [128 codes][64 k].
// Both passes (Ah*Bh, Al*Bh) accumulate into ONE fp32 accumulator = x*Bh exactly.
// Per-lane top-2 -> 32 lossless candidates/row; guard G = min lane v2.
// direct / exact rescue (<=8 cands, sequential recipe) / warp-per-row exact scan.
__global__ void __launch_bounds__(256, 1)
k_level(const float* __restrict__ z,
        const float* __restrict__ cb,     // fp32 codebook for this level
        int level,
        float* __restrict__ o_idx_f)
{
    extern __shared__ char smem[];
    uint32_t sb = smem_u32(smem);
    float* ee_s  = (float*)(smem + SO_EE);
    float* cv    = (float*)(smem + SO_CV);
    int*   cidx  = (int*)(smem + SO_CI);
    int*   s_idx = (int*)(smem + SO_IDX);
    float* s_red = (float*)(smem + SO_RED);
    int*   s_cnt = (int*)(smem + SO_CNT);
    int*   rq    = (int*)(smem + SO_RQ);
    int*   fq    = (int*)(smem + SO_FQ);

    const int tid = threadIdx.x, wid = tid >> 5, lane = tid & 31;
    const int wm = wid >> 2, wn = wid & 3;
    const int row0 = blockIdx.x * BM;
    const int first = (level == 0);
    const float* A_src = first ? z : g_resid;
    const __half* pbh = g_bh + (size_t)level * CBK * DIM;

    if (tid == 0) { s_cnt[0] = 0; s_cnt[1] = 0; }

    // ---- A tile: [128 rows][512 = xh(0-255)|xl(256-511)] fp16, 1024B rows, swizzled ----
    {
#pragma unroll
        for (int i = 0; i < 32; i++) {
            int ch = i * 256 + tid;
            int m = ch >> 6, kc = ch & 63;
            const __half* src = (kc < 32)
                ? (g_ah + (size_t)(row0 + m) * DIM + kc * 8)
                : (g_al + (size_t)(row0 + m) * DIM + (kc - 32) * 8);
            uint32_t dst = sb + SO_A + m * 1024 + ((kc * 16) ^ ((m & 7) << 4));
            CP16(dst, src);
        }
        CPCOMMIT();
    }
    for (int i = tid; i < CBK; i += 256) ee_s[i] = g_ee[level * CBK + i];

    const int q2   = (lane & 3) * 2;
    const int rthr = lane >> 2;
    const int arow = ((lane >> 3) & 1) * 8 + (lane & 7);
    const int kofA = (lane >> 4) * 8;
    const int brow = ((lane >> 4) & 1) * 8 + (lane & 7);
    const int kofB = ((lane >> 3) & 1) * 8;

    uint32_t aOff[4]; int aKey[4];
#pragma unroll
    for (int im = 0; im < 4; im++) {
        int m = wm * 64 + im * 16 + arow;
        aOff[im] = sb + SO_A + m * 1024;
        aKey[im] = (m & 7) << 4;
    }
    uint32_t bOff[2]; int bKey[2];
#pragma unroll
    for (int jg = 0; jg < 2; jg++) {
        int nr = wn * 32 + jg * 16 + brow;
        bOff[jg] = nr * 128;
        bKey[jg] = (nr & 7) << 4;
    }
    float xr[8];
#pragma unroll
    for (int i = 0; i < 8; i++)
        xr[i] = g_xx[row0 + wm * 64 + (i >> 1) * 16 + (i & 1) * 8 + rthr];

    float acc[4][4][4];
#pragma unroll
    for (int a = 0; a < 4; a++)
#pragma unroll
        for (int b = 0; b < 4; b++)
#pragma unroll
            for (int c = 0; c < 4; c++) acc[a][b][c] = 0.f;
    float v1[8], v2[8]; int i1[8], i2[8];
#pragma unroll
    for (int i = 0; i < 8; i++) { v1[i] = 3.4e38f; v2[i] = 3.4e38f; i1[i] = 1 << 29; i2[i] = 1 << 29; }

    // B slab s: codes [nt*128,+128), k [bs*64,+64); 16KB, 128B swizzled rows
    auto loadB = [&](int s) {
        int nt = s >> 2, bs = s & 3;
        uint32_t dB = sb + SO_B + (s & 1) * 16384;
#pragma unroll
        for (int i = 0; i < 4; i++) {
            int ch = i * 256 + tid;
            int r = ch >> 3, kc = ch & 7;
            CP16(dB + r * 128 + ((kc * 16) ^ ((r & 7) << 4)),
                 pbh + (size_t)(nt * 128 + r) * DIM + bs * 64 + kc * 8);
        }
        CPCOMMIT();
    };

    loadB(0);

#define UPD(rp, dval, cx) do { \
        if ((dval) < v1[rp]) { v2[rp] = v1[rp]; i2[rp] = i1[rp]; v1[rp] = (dval); i1[rp] = (cx); } \
        else if ((dval) < v2[rp]) { v2[rp] = (dval); i2[rp] = (cx); } } while (0)

    // ---- mainloop: 8 N-chunks (128 codes) x 4 k-slabs = 32 steps, 2 passes/slab ----
    for (int s = 0; s < 32; s++) {
        if (s + 1 < 32) { loadB(s + 1); CPWAIT1(); } else { CPWAIT0(); }
        __syncthreads();
        int nt = s >> 2, bs = s & 3;
        uint32_t bB = sb + SO_B + (s & 1) * 16384;
#pragma unroll
        for (int kc = 0; kc < 4; kc++) {
            uint32_t bf[2][4];
#pragma unroll
            for (int jg = 0; jg < 2; jg++)
                ldsm_x4(bf[jg], bB + bOff[jg] + ((((kc * 16 + kofB) << 1)) ^ bKey[jg]));
            uint32_t af[4][4];
            int kh = bs * 64 + kc * 16;                    // xh cols
#pragma unroll
            for (int im = 0; im < 4; im++)
                ldsm_x4(af[im], aOff[im] + ((((kh + kofA) << 1)) ^ aKey[im]));
#pragma unroll
            for (int im = 0; im < 4; im++) {
                mma_f16(acc[im][0], af[im], &bf[0][0]);
                mma_f16(acc[im][1], af[im], &bf[0][2]);
                mma_f16(acc[im][2], af[im], &bf[1][0]);
                mma_f16(acc[im][3], af[im], &bf[1][2]);
            }
            int kl = 256 + kh;                             // xl cols (2nd pass, same Bh)
#pragma unroll
            for (int im = 0; im < 4; im++)
                ldsm_x4(af[im], aOff[im] + ((((kl + kofA) << 1)) ^ aKey[im]));
#pragma unroll
            for (int im = 0; im < 4; im++) {
                mma_f16(acc[im][0], af[im], &bf[0][0]);
                mma_f16(acc[im][1], af[im], &bf[0][2]);
                mma_f16(acc[im][2], af[im], &bf[1][0]);
                mma_f16(acc[im][3], af[im], &bf[1][2]);
            }
        }
        if (bs == 3) {                                     // N-chunk done: score + top-2
#pragma unroll
            for (int im = 0; im < 4; im++)
#pragma unroll
                for (int jj = 0; jj < 4; jj++) {
                    int col = nt * 128 + wn * 32 + (jj >> 1) * 16 + (jj & 1) * 8 + q2;
                    float e0 = ee_s[col], e1 = ee_s[col + 1];
                    float d;
                    d = (xr[im * 2] + e0) - 2.0f * acc[im][jj][0];
                    UPD(im * 2, d, col);
                    d = (xr[im * 2] + e1) - 2.0f * acc[im][jj][1];
                    UPD(im * 2, d, col + 1);
                    d = (xr[im * 2 + 1] + e0) - 2.0f * acc[im][jj][2];
                    UPD(im * 2 + 1, d, col);
                    d = (xr[im * 2 + 1] + e1) - 2.0f * acc[im][jj][3];
                    UPD(im * 2 + 1, d, col + 1);
                    acc[im][jj][0] = 0.f; acc[im][jj][1] = 0.f;
                    acc[im][jj][2] = 0.f; acc[im][jj][3] = 0.f;
                }
        }
        __syncthreads();
    }

    // ---- every lane stores its top-2 (16 slots x 2 per row, lossless to 2nd order) ----
#pragma unroll
    for (int i = 0; i < 8; i++) {
        int row = wm * 64 + (i >> 1) * 16 + (i & 1) * 8 + rthr;
        int g = (wn * 4 + (lane & 3)) * 2;
        cv[row * 32 + g]     = v1[i];  cidx[row * 32 + g]     = i1[i];
        cv[row * 32 + g + 1] = v2[i];  cidx[row * 32 + g + 1] = i2[i];
    }
    __syncthreads();

    // ---- per-row decision (thread tid = row): direct / rescue / full-scan ----
    if (tid < 128) {
        float w0 = 3.4e38f; int x0 = 1 << 30; float G = 3.4e38f;
#pragma unroll 8
        for (int g2 = 0; g2 < 32; g2++) {
            float v = cv[tid * 32 + g2];
            int  ix = cidx[tid * 32 + g2];
            if (v < w0 || (v == w0 && ix < x0)) { w0 = v; x0 = ix; }
            if (g2 & 1) G = fminf(G, v);            // lane v2 entries
        }
        float T = w0 + MU;
        if (G <= T) {
            fq[atomicAdd(&s_cnt[1], 1)] = tid;      // uncaptured candidate may be in window
        } else {
            int n = 0, cand[8];
#pragma unroll 8
            for (int g2 = 0; g2 < 32; g2++) {
                float v = cv[tid * 32 + g2];
                if (v <= T) { if (n < 8) cand[n] = cidx[tid * 32 + g2]; n++; }
            }
            if (n > 8) {
                fq[atomicAdd(&s_cnt[1], 1)] = tid;
            } else if (n == 1) {                    // provably the reference winner
                s_idx[tid] = x0;
                int gr = row0 + tid;
                g_idx[(size_t)gr * LVL + level] = x0;
                if (o_idx_f) o_idx_f[(size_t)gr * LVL + level] = (float)x0;
            } else {                                // exact rescue among n cands
                int pos = atomicAdd(&s_cnt[0], 1);
                rq[pos * 12 + 0] = tid;
                rq[pos * 12 + 1] = n;
#pragma unroll
                for (int q = 0; q < 8; q++) rq[pos * 12 + 2 + q] = (q < n) ? cand[q] : 0;
            }
        }
    }
    __syncthreads();

    // ---- rescue: exact fp32 sequential-k dd for <=8 candidates (warp per entry) ----
    {
        int cnt = s_cnt[0];
        for (int e = wid; e < cnt; e += 8) {
            int row = rq[e * 12], n = rq[e * 12 + 1];
            float dd = 3.4e38f; int ci = 1 << 30;
            if (lane < n) {
                ci = rq[e * 12 + 2 + lane];
                const float* a  = A_src + (size_t)(row0 + row) * DIM;
                const float* ep = cb + (size_t)ci * DIM;
                float dot = 0.f;
#pragma unroll 4
                for (int k = 0; k < 256; k++) dot = fmaf(a[k], ep[k], dot);
                dd = (g_xx[row0 + row] + ee_s[ci]) - 2.0f * dot;
            }
#pragma unroll
            for (int o = 1; o <= 4; o <<= 1) {      // reduce over 8-lane group
                float ov = __shfl_xor_sync(0xffffffffu, dd, o);
                int   oi = __shfl_xor_sync(0xffffffffu, ci, o);
                if (ov < dd || (ov == dd && oi < ci)) { dd = ov; ci = oi; }
            }
            if (lane == 0) {
                s_idx[row] = ci;
                int gr = row0 + row;
                g_idx[(size_t)gr * LVL + level] = ci;
                if (o_idx_f) o_idx_f[(size_t)gr * LVL + level] = (float)ci;
            }
        }
    }

    // ---- full-scan: warp-per-row, exact sequential recipe, 2 interleaved chains ----
    {
        int fcnt = s_cnt[1];
        for (int e = wid; e < fcnt; e += 8) {
            int row = fq[e];
            const float* a = A_src + (size_t)(row0 + row) * DIM;
            float xxv = g_xx[row0 + row];
            float best = 3.4e38f; int bix = 1 << 30;
            for (int j = 0; j < 32; j += 2) {       // lane owns codes lane*32 .. +31
                int ca = lane * 32 + j, cb2 = ca + 1;
                const float* ea = cb + (size_t)ca * DIM;
                const float* eb = ea + DIM;
                float da = 0.f, db = 0.f;           // two independent sequential chains
#pragma unroll 4
                for (int k = 0; k < 256; k++) {
                    float av = a[k];
                    da = fmaf(av, ea[k], da);
                    db = fmaf(av, eb[k], db);
                }
                float s1 = (xxv + ee_s[ca]) - 2.0f * da;
                float s2 = (xxv + ee_s[cb2]) - 2.0f * db;
                if (s1 < best) { best = s1; bix = ca; }
                if (s2 < best) { best = s2; bix = cb2; }
            }
#pragma unroll
            for (int o = 16; o; o >>= 1) {
                float ov = __shfl_xor_sync(0xffffffffu, best, o);
                int   oi = __shfl_xor_sync(0xffffffffu, bix, o);
                if (ov < best || (ov == best && oi < bix)) { best = ov; bix = oi; }
            }
            if (!lane) {
                s_idx[row] = bix;
                int gr = row0 + row;
                g_idx[(size_t)gr * LVL + level] = bix;
                if (o_idx_f) o_idx_f[(size_t)gr * LVL + level] = (float)bix;
            }
        }
    }
    __syncthreads();

    // ---- fused epilogue: residual, qsum, fp16 hi/lo for next level, xx, commit ----
    {
        int r2 = tid >> 1, dh2 = (tid & 1) << 7;    // 2 threads/row, 128 dims each
        int gi = s_idx[r2];
        const float* ev = cb + (size_t)gi * DIM + dh2;
        size_t gofs = (size_t)(row0 + r2) * DIM + dh2;
        const float* av = A_src + gofs;
        float* ro = g_resid + gofs;
        float* qo = g_qsum + gofs;
        __half* ho = g_ah + gofs;
        __half* lo = g_al + gofs;
        float ss = 0.f;
#pragma unroll 4
        for (int j = 0; j < 32; j++) {
            float4 a = *(const float4*)(av + j * 4);
            float4 e = *(const float4*)(ev + j * 4);
            float4 rn = make_float4(a.x - e.x, a.y - e.y, a.z - e.z, a.w - e.w);
            *(float4*)(ro + j * 4) = rn;
            float4 q;
            if (first) q = e;
            else {
                float4 qp = *(const float4*)(qo + j * 4);
                q = make_float4(qp.x + e.x, qp.y + e.y, qp.z + e.z, qp.w + e.w);
            }
            *(float4*)(qo + j * 4) = q;
            __half h0 = __float2half_rn(rn.x), h1 = __float2half_rn(rn.y);
            __half h2 = __float2half_rn(rn.z), h3 = __float2half_rn(rn.w);
            ho[j * 4 + 0] = h0; ho[j * 4 + 1] = h1; ho[j * 4 + 2] = h2; ho[j * 4 + 3] = h3;
            lo[j * 4 + 0] = __float2half_rn(rn.x - __half2float(h0));
            lo[j * 4 + 1] = __float2half_rn(rn.y - __half2float(h1));
            lo[j * 4 + 2] = __float2half_rn(rn.z - __half2float(h2));
            lo[j * 4 + 3] = __float2half_rn(rn.w - __half2float(h3));
            ss = fmaf(rn.x, rn.x, ss); ss = fmaf(rn.y, rn.y, ss);
            ss = fmaf(rn.z, rn.z, ss); ss = fmaf(rn.w, rn.w, ss);
        }
        s_red[tid] = ss;
        __syncthreads();
        if (!(tid & 1)) g_xx[row0 + r2] = s_red[tid] + s_red[tid | 1];
        __syncthreads();
#pragma unroll
        for (int o = 128; o; o >>= 1) {
            if (tid < o) s_red[tid] += s_red[tid + o];
            __syncthreads();
        }
        if (!tid) g_commit_part[level * GRID + blockIdx.x] = s_red[0];
    }
#undef UPD
}

// ---------------- histogram ----------------
__global__ void k_count()
{
    __shared__ int h[CBK];
    for (int i = threadIdx.x; i < CBK; i += blockDim.x) h[i] = 0;
    __syncthreads();
    int stride = gridDim.x * blockDim.x;
    for (int i = blockIdx.x * blockDim.x + threadIdx.x; i < BATCH * LVL; i += stride)
        atomicAdd(&h[g_idx[i]], 1);
    __syncthreads();
    for (int i = threadIdx.x; i < CBK; i += blockDim.x) {
        int v = h[i];
        if (v) atomicAdd(&g_counts[i], v);
    }
}

// ---------------- z_q ----------------
__global__ void k_zq(const float* __restrict__ z, float* __restrict__ out)
{
    int n = BATCH * DIM / 4;
    for (int i = blockIdx.x * blockDim.x + threadIdx.x; i < n; i += gridDim.x * blockDim.x) {
        float4 zv = ((const float4*)z)[i];
        float4 qv = ((const float4*)g_qsum)[i];
        float4 t = make_float4(qv.x - zv.x, qv.y - zv.y, qv.z - zv.z, qv.w - zv.w);
        ((float4*)out)[i] = make_float4(zv.x + t.x, zv.y + t.y, zv.z + t.z, zv.w + t.w);
    }
}

// ---------------- scalars ----------------
__global__ void k_final(float* __restrict__ o_sc)
{
    __shared__ float se[1024];
    __shared__ float sc[LVL];
    int t = threadIdx.x;
    float p = (float)g_counts[t] / 262144.0f;
    se[t] = (p > 0.f) ? p * logf(p + 1e-10f) : 0.f;
    __syncthreads();
#pragma unroll
    for (int o = 512; o; o >>= 1) {
        if (t < o) se[t] += se[t + o];
        __syncthreads();
    }
    int w = t >> 5, lane = t & 31;
    if (w < LVL) {
        float s = 0.f;
        for (int b = lane; b < GRID; b += 32) s += g_commit_part[w * GRID + b];
#pragma unroll
        for (int o = 16; o; o >>= 1) s += __shfl_xor_sync(0xffffffffu, s, o);
        if (!lane) sc[w] = s;
    }
    __syncthreads();
    if (!t && o_sc) {
        float ent = -se[0];
        float total = 0.f;
        for (int l = 0; l < LVL; l++) total += sc[l] / 8388608.0f;
        o_sc[0] = 0.25f * total;
        o_sc[1] = total;
        o_sc[2] = expf(ent);
    }
}

// ---------------- launch ----------------
extern "C" void kernel_launch(void* const* d_in, const int* in_sizes, int n_in,
                              void* d_out, int out_size)
{
    const float* z   = (const float*)d_in[0];
    const float* emb = (const float*)d_in[1];
    if (n_in >= 2 && in_sizes[0] == LVL * CBK * DIM && in_sizes[1] == BATCH * DIM) {
        emb = (const float*)d_in[0];
        z   = (const float*)d_in[1];
    }

    cudaFuncSetAttribute(k_level, cudaFuncAttributeMaxDynamicSharedMemorySize, SMEM_BYTES);

    float* out = (float*)d_out;
    const long NZQ = (long)BATCH * DIM;   // 8388608
    const long NI  = (long)BATCH * LVL;   // 262144
    float* o_zq  = ((long)out_size >= NZQ)          ? out             : nullptr;
    float* o_idx = ((long)out_size >= NZQ + NI)     ? out + NZQ       : nullptr;
    float* o_sc  = ((long)out_size >= NZQ + NI + 3) ? out + NZQ + NI  : nullptr;

    k_prepB<<<(LVL * CBK * DIM) / 256, 256>>>(emb);
    k_eeinit<<<(LVL * CBK) / 8, 256>>>(emb);
    k_prepA<<<BATCH / 8, 256>>>(z);
    for (int l = 0; l < LVL; l++)
        k_level<<<GRID, 256, SMEM_BYTES>>>(z, emb + (size_t)l * CBK * DIM, l, o_idx);
    k_count<<<64, 256>>>();
    if (o_zq) k_zq<<<2048, 256>>>(z, o_zq);
    k_final<<<1, 1024>>>(o_sc);
}

// round 16
// speedup vs baseline: 4.3751x; 4.3751x over previous
#include <cuda_runtime.h>
#include <cuda_bf16.h>
#include <math.h>
#include <stdint.h>

#define BATCH 32768
#define DIM   256
#define CBK   1024
#define LVL   8
#define BM    64
#define GRID  (BATCH / BM)           // 512
#define MU    1e-4f                  // rescue margin (3-pass hard error bound ~1e-6)

// smem byte offsets
#define SO_A    0                    // A tile [64 rows][512 = hi|lo] bf16, 1024B rows = 65536
#define SO_B    65536                // B slabs 2 x [128 codes][64 k] bf16 = 32768
#define SO_EE   98304                // 1024 floats = 4096
#define SO_SV   102400               // 4 n-warps x 64 rows x 2 = 2048
#define SO_SI   104448               // same, ints = 2048
#define SO_IDX  106496               // 64 ints = 256
#define SO_RED  106752               // 256 floats = 1024
#define SO_CNT  107776               // rescue counter (+pad)
#define SO_RQ   107792               // 64 entries x 6 ints = 1536
#define SMEM_BYTES 109328            // x2 CTAs = 218656 <= SM smem

// ---------------- device scratch ----------------
__device__ float g_resid[BATCH * DIM];
__device__ float g_qsum [BATCH * DIM];
__device__ float g_xx   [BATCH];
__device__ float g_ee   [LVL * CBK];
__device__ int   g_idx  [BATCH * LVL];
__device__ float g_commit_part[LVL * GRID];
__device__ int   g_counts[CBK];
__device__ __nv_bfloat16 g_ah[BATCH * DIM];        // residual hi
__device__ __nv_bfloat16 g_al[BATCH * DIM];        // residual lo
__device__ __nv_bfloat16 g_bh[LVL * CBK * DIM];    // codebook hi
__device__ __nv_bfloat16 g_bl[LVL * CBK * DIM];    // codebook lo

// ---------------- helpers ----------------
__device__ __forceinline__ uint32_t smem_u32(const void* p) {
    uint32_t a;
    asm("{ .reg .u64 t; cvta.to.shared.u64 t, %1; cvt.u32.u64 %0, t; }" : "=r"(a) : "l"(p));
    return a;
}
#define CP16(dst, src) asm volatile("cp.async.cg.shared.global [%0], [%1], 16;" :: "r"(dst), "l"(src))
#define CPCOMMIT()     asm volatile("cp.async.commit_group;" ::: "memory")
#define CPWAIT1()      asm volatile("cp.async.wait_group 1;" ::: "memory")
#define CPWAIT0()      asm volatile("cp.async.wait_group 0;" ::: "memory")

__device__ __forceinline__ void ldsm_x4(uint32_t* r, uint32_t addr) {
    asm volatile("ldmatrix.sync.aligned.m8n8.x4.shared.b16 {%0,%1,%2,%3}, [%4];"
        : "=r"(r[0]), "=r"(r[1]), "=r"(r[2]), "=r"(r[3]) : "r"(addr));
}
__device__ __forceinline__ void mma_bf16(float* d, const uint32_t* a, const uint32_t* b) {
    asm volatile("mma.sync.aligned.m16n8k16.row.col.f32.bf16.bf16.f32 "
        "{%0,%1,%2,%3}, {%4,%5,%6,%7}, {%8,%9}, {%0,%1,%2,%3};"
        : "+f"(d[0]), "+f"(d[1]), "+f"(d[2]), "+f"(d[3])
        : "r"(a[0]), "r"(a[1]), "r"(a[2]), "r"(a[3]), "r"(b[0]), "r"(b[1]));
}

// ---------------- prep kernels ----------------
__global__ void k_prepB(const float* __restrict__ emb)
{
    int i = blockIdx.x * blockDim.x + threadIdx.x;
    if (i >= LVL * CBK * DIM) return;
    float x = emb[i];
    __nv_bfloat16 h = __float2bfloat16(x);
    g_bh[i] = h;
    g_bl[i] = __float2bfloat16(x - __bfloat162float(h));
}

__global__ void k_eeinit(const float* __restrict__ emb)
{
    int gt = blockIdx.x * blockDim.x + threadIdx.x;
    if (gt < CBK) g_counts[gt] = 0;
    int gw   = blockIdx.x * (blockDim.x >> 5) + (threadIdx.x >> 5);
    int lane = threadIdx.x & 31;
    if (gw >= LVL * CBK) return;
    const float* r = emb + (size_t)gw * DIM;
    float s = 0.f;
#pragma unroll
    for (int j = 0; j < 8; j++) { float v = r[lane + 32 * j]; s = fmaf(v, v, s); }
#pragma unroll
    for (int o = 16; o; o >>= 1) s += __shfl_xor_sync(0xffffffffu, s, o);
    if (!lane) g_ee[gw] = s;
}

__global__ void k_prepA(const float* __restrict__ z)
{
    int gw   = blockIdx.x * (blockDim.x >> 5) + (threadIdx.x >> 5);
    int lane = threadIdx.x & 31;
    if (gw >= BATCH) return;
    const float* r = z + (size_t)gw * DIM;
    float s = 0.f;
#pragma unroll
    for (int j = 0; j < 8; j++) {
        float v = r[lane + 32 * j];
        __nv_bfloat16 h = __float2bfloat16(v);
        g_ah[(size_t)gw * DIM + lane + 32 * j] = h;
        g_al[(size_t)gw * DIM + lane + 32 * j] = __float2bfloat16(v - __bfloat162float(h));
        s = fmaf(v, v, s);
    }
#pragma unroll
    for (int o = 16; o; o >>= 1) s += __shfl_xor_sync(0xffffffffu, s, o);
    if (!lane) g_xx[gw] = s;
}

// ---------------- main per-level kernel: 3-pass bf16 HMMA, 2 CTAs/SM -------------
// 512 CTAs x 256 threads, 2 CTAs/SM (smem 107KB, regs capped 128). 8 warps = 2m x 4n,
// warp tile 32x32 (acc[2][4][4] = 32 regs). A [64][512 hi|lo] resident; B slabs
// [128 codes][64 k] double-buffered, bs 0-3 Bh (hh+lh passes), 4-7 Bl (hl pass).
// Decision logic identical to the bit-exact round-9 kernel: per-thread top-2,
// 4-lane merge, per-n-warp smem top-2, global top-3, MU margin, <=3-cand rescue.
__global__ void __launch_bounds__(256, 2)
k_level(const float* __restrict__ z,
        const float* __restrict__ cb,
        int level,
        float* __restrict__ o_idx_f)
{
    extern __shared__ char smem[];
    uint32_t sb = smem_u32(smem);
    float* ee_s  = (float*)(smem + SO_EE);
    float* sv    = (float*)(smem + SO_SV);
    int*   si    = (int*)(smem + SO_SI);
    int*   s_idx = (int*)(smem + SO_IDX);
    float* s_red = (float*)(smem + SO_RED);
    int*   s_cnt = (int*)(smem + SO_CNT);
    int*   rq    = (int*)(smem + SO_RQ);

    const int tid = threadIdx.x, wid = tid >> 5, lane = tid & 31;
    const int wm = wid >> 2, wn = wid & 3;
    const int row0 = blockIdx.x * BM;
    const int first = (level == 0);
    const float* A_src = first ? z : g_resid;
    const __nv_bfloat16* pbh = g_bh + (size_t)level * CBK * DIM;
    const __nv_bfloat16* pbl = g_bl + (size_t)level * CBK * DIM;

    if (tid == 0) *s_cnt = 0;

    // ---- A tile: [64 rows][512 = hi(0-255)|lo(256-511)] bf16, 1024B rows, swizzled ----
    {
#pragma unroll
        for (int i = 0; i < 16; i++) {
            int ch = i * 256 + tid;                  // 4096 chunks of 16B
            int m = ch >> 6, kc = ch & 63;
            const __nv_bfloat16* src = (kc < 32)
                ? (g_ah + (size_t)(row0 + m) * DIM + kc * 8)
                : (g_al + (size_t)(row0 + m) * DIM + (kc - 32) * 8);
            uint32_t dst = sb + SO_A + m * 1024 + ((kc * 16) ^ ((m & 7) << 4));
            CP16(dst, src);
        }
        CPCOMMIT();
    }
    for (int i = tid; i < CBK; i += 256) ee_s[i] = g_ee[level * CBK + i];

    const int q2   = (lane & 3) * 2;
    const int rthr = lane >> 2;
    const int arow = ((lane >> 3) & 1) * 8 + (lane & 7);
    const int kofA = (lane >> 4) * 8;
    const int brow = ((lane >> 4) & 1) * 8 + (lane & 7);
    const int kofB = ((lane >> 3) & 1) * 8;

    uint32_t aOff[2]; int aKey[2];
#pragma unroll
    for (int im = 0; im < 2; im++) {
        int m = wm * 32 + im * 16 + arow;
        aOff[im] = sb + SO_A + m * 1024;
        aKey[im] = (m & 7) << 4;
    }
    uint32_t bOff[2]; int bKey[2];
#pragma unroll
    for (int jg = 0; jg < 2; jg++) {
        int nr = wn * 32 + jg * 16 + brow;
        bOff[jg] = nr * 128;
        bKey[jg] = (nr & 7) << 4;
    }
    float xr[4];
#pragma unroll
    for (int i = 0; i < 4; i++)
        xr[i] = g_xx[row0 + wm * 32 + (i >> 1) * 16 + (i & 1) * 8 + rthr];

    float acc[2][4][4];
#pragma unroll
    for (int a = 0; a < 2; a++)
#pragma unroll
        for (int b = 0; b < 4; b++)
#pragma unroll
            for (int c = 0; c < 4; c++) acc[a][b][c] = 0.f;
    float v1[4], v2[4]; int i1[4], i2[4];
#pragma unroll
    for (int i = 0; i < 4; i++) { v1[i] = 3.4e38f; v2[i] = 3.4e38f; i1[i] = 1 << 29; i2[i] = 1 << 29; }

    // B slab s: codes [nt*128,+128), k-quarter (bs&3); bs 0-3 from Bh, 4-7 from Bl
    auto loadB = [&](int s) {
        int nt = s >> 3, bs = s & 7;
        const __nv_bfloat16* srcB = ((bs < 4) ? pbh : pbl)
            + (size_t)(nt * 128) * DIM + (bs & 3) * 64;
        uint32_t dB = sb + SO_B + (s & 1) * 16384;
#pragma unroll
        for (int i = 0; i < 4; i++) {
            int ch = i * 256 + tid;
            int r = ch >> 3, kc = ch & 7;
            CP16(dB + r * 128 + ((kc * 16) ^ ((r & 7) << 4)),
                 srcB + (size_t)r * DIM + kc * 8);
        }
        CPCOMMIT();
    };

    loadB(0);

#define UPD(rp, dval, cx) do { \
        if ((dval) < v1[rp]) { v2[rp] = v1[rp]; i2[rp] = i1[rp]; v1[rp] = (dval); i1[rp] = (cx); } \
        else if ((dval) < v2[rp]) { v2[rp] = (dval); i2[rp] = (cx); } } while (0)

    // ---- mainloop: 8 N-chunks x 8 B-slabs = 64 steps ----
    for (int s = 0; s < 64; s++) {
        if (s + 1 < 64) { loadB(s + 1); CPWAIT1(); } else { CPWAIT0(); }
        __syncthreads();
        int nt = s >> 3, bs = s & 7;
        uint32_t bB = sb + SO_B + (s & 1) * 16384;
#pragma unroll
        for (int kc = 0; kc < 4; kc++) {
            uint32_t bf[2][4];
#pragma unroll
            for (int jg = 0; jg < 2; jg++)
                ldsm_x4(bf[jg], bB + bOff[jg] + ((((kc * 16 + kofB) << 1)) ^ bKey[jg]));
            uint32_t af[2][4];
            int kh = (bs & 3) * 64 + kc * 16;        // Ah cols (hh for bs<4, hl for bs>=4)
#pragma unroll
            for (int im = 0; im < 2; im++)
                ldsm_x4(af[im], aOff[im] + ((((kh + kofA) << 1)) ^ aKey[im]));
#pragma unroll
            for (int im = 0; im < 2; im++) {
                mma_bf16(acc[im][0], af[im], &bf[0][0]);
                mma_bf16(acc[im][1], af[im], &bf[0][2]);
                mma_bf16(acc[im][2], af[im], &bf[1][0]);
                mma_bf16(acc[im][3], af[im], &bf[1][2]);
            }
            if (bs < 4) {                             // lh pass shares this Bh slab
                int kl = 256 + (bs & 3) * 64 + kc * 16;  // Al cols
#pragma unroll
                for (int im = 0; im < 2; im++)
                    ldsm_x4(af[im], aOff[im] + ((((kl + kofA) << 1)) ^ aKey[im]));
#pragma unroll
                for (int im = 0; im < 2; im++) {
                    mma_bf16(acc[im][0], af[im], &bf[0][0]);
                    mma_bf16(acc[im][1], af[im], &bf[0][2]);
                    mma_bf16(acc[im][2], af[im], &bf[1][0]);
                    mma_bf16(acc[im][3], af[im], &bf[1][2]);
                }
            }
        }
        if (bs == 7) {                                // N-chunk done: score + top-2
#pragma unroll
            for (int im = 0; im < 2; im++)
#pragma unroll
                for (int jj = 0; jj < 4; jj++) {
                    int col = nt * 128 + wn * 32 + (jj >> 1) * 16 + (jj & 1) * 8 + q2;
                    float e0 = ee_s[col], e1 = ee_s[col + 1];
                    float d;
                    d = (xr[im * 2] + e0) - 2.0f * acc[im][jj][0];
                    UPD(im * 2, d, col);
                    d = (xr[im * 2] + e1) - 2.0f * acc[im][jj][1];
                    UPD(im * 2, d, col + 1);
                    d = (xr[im * 2 + 1] + e0) - 2.0f * acc[im][jj][2];
                    UPD(im * 2 + 1, d, col);
                    d = (xr[im * 2 + 1] + e1) - 2.0f * acc[im][jj][3];
                    UPD(im * 2 + 1, d, col + 1);
                    acc[im][jj][0] = 0.f; acc[im][jj][1] = 0.f;
                    acc[im][jj][2] = 0.f; acc[im][jj][3] = 0.f;
                }
        }
        __syncthreads();
    }

    // ---- top-2 merge across the 4 q2-lanes, store per-n-warp top-2 to smem ----
#pragma unroll
    for (int i = 0; i < 4; i++) {
        float a1 = v1[i], a2 = v2[i]; int b1 = i1[i], b2 = i2[i];
#pragma unroll
        for (int o = 1; o <= 2; o <<= 1) {
            float u1 = __shfl_xor_sync(0xffffffffu, a1, o);
            float u2 = __shfl_xor_sync(0xffffffffu, a2, o);
            int   j1 = __shfl_xor_sync(0xffffffffu, b1, o);
            int   j2 = __shfl_xor_sync(0xffffffffu, b2, o);
            if (u1 < a1 || (u1 == a1 && j1 < b1)) {
                if (a1 < u2 || (a1 == u2 && b1 < j2)) { a2 = a1; b2 = b1; }
                else                                  { a2 = u2; b2 = j2; }
                a1 = u1; b1 = j1;
            } else {
                if (u1 < a2 || (u1 == a2 && j1 < b2)) { a2 = u1; b2 = j1; }
            }
        }
        if ((lane & 3) == 0) {
            int row = wm * 32 + (i >> 1) * 16 + (i & 1) * 8 + rthr;
            sv[wn * 128 + row * 2]     = a1; si[wn * 128 + row * 2]     = b1;
            sv[wn * 128 + row * 2 + 1] = a2; si[wn * 128 + row * 2 + 1] = b2;
        }
    }
    __syncthreads();

    // ---- per-row global top-3 scan + rescue decision (thread tid = row) ----
    if (tid < BM) {
        float w0 = 3.4e38f, w1 = 3.4e38f, w2 = 3.4e38f;
        int   x0 = 1 << 30, x1 = 1 << 30, x2 = 1 << 30;
#pragma unroll
        for (int w = 0; w < 4; w++)
#pragma unroll
            for (int s2 = 0; s2 < 2; s2++) {
                float v = sv[w * 128 + tid * 2 + s2];
                int  ix = si[w * 128 + tid * 2 + s2];
                if (v < w0 || (v == w0 && ix < x0)) {
                    w2 = w1; x2 = x1; w1 = w0; x1 = x0; w0 = v; x0 = ix;
                } else if (v < w1 || (v == w1 && ix < x1)) {
                    w2 = w1; x2 = x1; w1 = v; x1 = ix;
                } else if (v < w2 || (v == w2 && ix < x2)) {
                    w2 = v; x2 = ix;
                }
            }
        if (w1 > w0 + MU) {                 // provably unambiguous
            s_idx[tid] = x0;
            int gr = row0 + tid;
            g_idx[(size_t)gr * LVL + level] = x0;
            if (o_idx_f) o_idx_f[(size_t)gr * LVL + level] = (float)x0;
        } else {
            int pos = atomicAdd(s_cnt, 1);
            rq[pos * 6 + 0] = tid;
            rq[pos * 6 + 1] = (w2 <= w0 + MU) ? 3 : 2;
            rq[pos * 6 + 2] = x0; rq[pos * 6 + 3] = x1; rq[pos * 6 + 4] = x2;
        }
    }
    __syncthreads();

    // ---- rescue: exact fp32 sequential-k dd for queued candidates ----
    {
        int cnt = *s_cnt;
        for (int e = wid; e < cnt; e += 8) {
            int row = rq[e * 6], n = rq[e * 6 + 1];
            float dd = 3.4e38f; int ci = 1 << 30;
            if (lane < n) {
                ci = rq[e * 6 + 2 + lane];
                const float* a  = A_src + (size_t)(row0 + row) * DIM;
                const float* ep = cb + (size_t)ci * DIM;
                float dot = 0.f;
#pragma unroll 4
                for (int k = 0; k < 256; k++) dot = fmaf(a[k], ep[k], dot);
                dd = (g_xx[row0 + row] + ee_s[ci]) - 2.0f * dot;
            }
#pragma unroll
            for (int o = 1; o <= 2; o <<= 1) {
                float ov = __shfl_xor_sync(0xffffffffu, dd, o);
                int   oi = __shfl_xor_sync(0xffffffffu, ci, o);
                if (ov < dd || (ov == dd && oi < ci)) { dd = ov; ci = oi; }
            }
            if (lane == 0) {
                s_idx[row] = ci;
                int gr = row0 + row;
                g_idx[(size_t)gr * LVL + level] = ci;
                if (o_idx_f) o_idx_f[(size_t)gr * LVL + level] = (float)ci;
            }
        }
    }
    __syncthreads();

    // ---- fused epilogue: residual, qsum, bf16 hi/lo for next level, xx, commit ----
    {
        int r4 = tid >> 2, dq = (tid & 3) << 6;     // 4 threads/row, 64 dims each
        int gi = s_idx[r4];
        const float* ev = cb + (size_t)gi * DIM + dq;
        size_t gofs = (size_t)(row0 + r4) * DIM + dq;
        const float* av = A_src + gofs;
        float* ro = g_resid + gofs;
        float* qo = g_qsum + gofs;
        __nv_bfloat162* ho  = (__nv_bfloat162*)(g_ah + gofs);
        __nv_bfloat162* lo2 = (__nv_bfloat162*)(g_al + gofs);
        float ss = 0.f;
#pragma unroll 4
        for (int j = 0; j < 16; j++) {
            float4 a = *(const float4*)(av + j * 4);
            float4 e = *(const float4*)(ev + j * 4);
            float4 rn = make_float4(a.x - e.x, a.y - e.y, a.z - e.z, a.w - e.w);
            *(float4*)(ro + j * 4) = rn;
            float4 q;
            if (first) q = e;
            else {
                float4 qp = *(const float4*)(qo + j * 4);
                q = make_float4(qp.x + e.x, qp.y + e.y, qp.z + e.z, qp.w + e.w);
            }
            *(float4*)(qo + j * 4) = q;
            __nv_bfloat162 h0 = __floats2bfloat162_rn(rn.x, rn.y);
            __nv_bfloat162 h1 = __floats2bfloat162_rn(rn.z, rn.w);
            __nv_bfloat162 l0 = __floats2bfloat162_rn(rn.x - __bfloat162float(h0.x),
                                                      rn.y - __bfloat162float(h0.y));
            __nv_bfloat162 l1 = __floats2bfloat162_rn(rn.z - __bfloat162float(h1.x),
                                                      rn.w - __bfloat162float(h1.y));
            ho[j * 2] = h0; ho[j * 2 + 1] = h1;
            lo2[j * 2] = l0; lo2[j * 2 + 1] = l1;
            ss = fmaf(rn.x, rn.x, ss); ss = fmaf(rn.y, rn.y, ss);
            ss = fmaf(rn.z, rn.z, ss); ss = fmaf(rn.w, rn.w, ss);
        }
        s_red[tid] = ss;
        __syncthreads();
        if (!(tid & 3))
            g_xx[row0 + r4] = (s_red[tid] + s_red[tid + 1]) + (s_red[tid + 2] + s_red[tid + 3]);
        __syncthreads();
#pragma unroll
        for (int o = 128; o; o >>= 1) {
            if (tid < o) s_red[tid] += s_red[tid + o];
            __syncthreads();
        }
        if (!tid) g_commit_part[level * GRID + blockIdx.x] = s_red[0];
    }
#undef UPD
}

// ---------------- histogram ----------------
__global__ void k_count()
{
    __shared__ int h[CBK];
    for (int i = threadIdx.x; i < CBK; i += blockDim.x) h[i] = 0;
    __syncthreads();
    int stride = gridDim.x * blockDim.x;
    for (int i = blockIdx.x * blockDim.x + threadIdx.x; i < BATCH * LVL; i += stride)
        atomicAdd(&h[g_idx[i]], 1);
    __syncthreads();
    for (int i = threadIdx.x; i < CBK; i += blockDim.x) {
        int v = h[i];
        if (v) atomicAdd(&g_counts[i], v);
    }
}

// ---------------- z_q ----------------
__global__ void k_zq(const float* __restrict__ z, float* __restrict__ out)
{
    int n = BATCH * DIM / 4;
    for (int i = blockIdx.x * blockDim.x + threadIdx.x; i < n; i += gridDim.x * blockDim.x) {
        float4 zv = ((const float4*)z)[i];
        float4 qv = ((const float4*)g_qsum)[i];
        float4 t = make_float4(qv.x - zv.x, qv.y - zv.y, qv.z - zv.z, qv.w - zv.w);
        ((float4*)out)[i] = make_float4(zv.x + t.x, zv.y + t.y, zv.z + t.z, zv.w + t.w);
    }
}

// ---------------- scalars ----------------
__global__ void k_final(float* __restrict__ o_sc)
{
    __shared__ float se[1024];
    __shared__ float sc[LVL];
    int t = threadIdx.x;
    float p = (float)g_counts[t] / 262144.0f;
    se[t] = (p > 0.f) ? p * logf(p + 1e-10f) : 0.f;
    __syncthreads();
#pragma unroll
    for (int o = 512; o; o >>= 1) {
        if (t < o) se[t] += se[t + o];
        __syncthreads();
    }
    int w = t >> 5, lane = t & 31;
    if (w < LVL) {
        float s = 0.f;
        for (int b = lane; b < GRID; b += 32) s += g_commit_part[w * GRID + b];
#pragma unroll
        for (int o = 16; o; o >>= 1) s += __shfl_xor_sync(0xffffffffu, s, o);
        if (!lane) sc[w] = s;
    }
    __syncthreads();
    if (!t && o_sc) {
        float ent = -se[0];
        float total = 0.f;
        for (int l = 0; l < LVL; l++) total += sc[l] / 8388608.0f;
        o_sc[0] = 0.25f * total;
        o_sc[1] = total;
        o_sc[2] = expf(ent);
    }
}

// ---------------- launch ----------------
extern "C" void kernel_launch(void* const* d_in, const int* in_sizes, int n_in,
                              void* d_out, int out_size)
{
    const float* z   = (const float*)d_in[0];
    const float* emb = (const float*)d_in[1];
    if (n_in >= 2 && in_sizes[0] == LVL * CBK * DIM && in_sizes[1] == BATCH * DIM) {
        emb = (const float*)d_in[0];
        z   = (const float*)d_in[1];
    }

    cudaFuncSetAttribute(k_level, cudaFuncAttributeMaxDynamicSharedMemorySize, SMEM_BYTES);

    float* out = (float*)d_out;
    const long NZQ = (long)BATCH * DIM;   // 8388608
    const long NI  = (long)BATCH * LVL;   // 262144
    float* o_zq  = ((long)out_size >= NZQ)          ? out             : nullptr;
    float* o_idx = ((long)out_size >= NZQ + NI)     ? out + NZQ       : nullptr;
    float* o_sc  = ((long)out_size >= NZQ + NI + 3) ? out + NZQ + NI  : nullptr;

    k_prepB<<<(LVL * CBK * DIM) / 256, 256>>>(emb);
    k_eeinit<<<(LVL * CBK) / 8, 256>>>(emb);
    k_prepA<<<BATCH / 8, 256>>>(z);
    for (int l = 0; l < LVL; l++)
        k_level<<<GRID, 256, SMEM_BYTES>>>(z, emb + (size_t)l * CBK * DIM, l, o_idx);
    k_count<<<64, 256>>>();
    if (o_zq) k_zq<<<2048, 256>>>(z, o_zq);
    k_final<<<1, 1024>>>(o_sc);
}